// round 10
// baseline (speedup 1.0000x reference)
#include <cuda_runtime.h>
#include <math.h>

#define IMG_H 2048
#define IMG_W 2048
#define HW (IMG_H * IMG_W)
#define THRESH 10.0f

// 180 / 3.14159 (reference constant, NOT pi)
#define RAD2DEG_D 57.29582790879777437539

// Octant boundary tangents (see R7 derivation)
#define T1_POS 0.41421317376f
#define T2_POS 2.41420677f
#define T1_NEG 0.41421628f
#define T2_NEG 2.41422489f
#define BAND1 1.0e-3f
#define BAND2 6.0e-3f

// Tile: 32 wide x 64 tall, 512 threads.
//   hbuf[c][r][s]    : h-sum at image (by0-4+r, bx0-2+s), r 0..71, s 0..35
//   sblur[c][r][s+4] : blurred at image (by0-2+r, bx0-2+s), r 0..67, s 0..35
//   smag[r][s+4]     : grad mag at image (by0-1+r, bx0-1+s), r 0..65, s 0..33
//   sk[y][x]         : quantized orientation for central pixel (y,x), y 0..63
#define TH 64
struct Smem {
    union {
        float hbuf[3][TH + 8][36];
        struct {
            float smag[TH + 2][44];
            signed char sk[TH][32];
        } b;
    } u;
    float sblur[3][TH + 4][44];
};

__device__ __forceinline__ float ldz_g(const float* __restrict__ p, int Y, int X) {
    return (Y >= 0 && Y < IMG_H && X >= 0 && X < IMG_W) ? __ldg(p + Y * IMG_W + X) : 0.0f;
}

__device__ __forceinline__ float sqrt_approx(float x) {
    float r;
    asm("sqrt.approx.f32 %0, %1;" : "=f"(r) : "f"(x));
    return r;
}

// ---------------------------------------------------------------------------
// Exact (fp64) helpers. (y,x) central coords: image (by0+y, bx0+x) =
// sblur[c][y+2][x+6].
// ---------------------------------------------------------------------------
__device__ __noinline__ void sobel_exact_smem(const float (*sb)[TH + 4][44],
                                              int y, int x,
                                              double& ogx, double& ogy, double& omag) {
    double gxs = 0.0, gys = 0.0, mg = 0.0;
#pragma unroll
    for (int c = 0; c < 3; c++) {
        const double a  = sb[c][y + 1][x + 5];
        const double b  = sb[c][y + 1][x + 6];
        const double cc = sb[c][y + 1][x + 7];
        const double d  = sb[c][y + 2][x + 5];
        const double e  = sb[c][y + 2][x + 7];
        const double f  = sb[c][y + 3][x + 5];
        const double g  = sb[c][y + 3][x + 6];
        const double h  = sb[c][y + 3][x + 7];
        const double gx = (a - cc) + 2.0 * (d - e) + (f - h);
        const double gy = (a + 2.0 * b + cc) - (f + 2.0 * g + h);
        gxs += gx; gys += gy;
        mg += sqrt(gx * gx + gy * gy);
    }
    ogx = gxs; ogy = gys; omag = mg;
}

__device__ __noinline__ int orient_k_exact_smem(const float (*sb)[TH + 4][44],
                                                int y, int x) {
    double gx, gy, m;
    sobel_exact_smem(sb, y, x, gx, gy, m);
    const double orient = atan2(gy, gx) * RAD2DEG_D + 180.0;
    return (int)rint(orient / 45.0);
}

__device__ __noinline__ double mag_exact_smem(const float (*sb)[TH + 4][44],
                                              int y, int x, int Y, int X) {
    if (X < 0 || X >= IMG_W || Y < 0 || Y >= IMG_H) return 0.0;
    double gx, gy, m;
    sobel_exact_smem(sb, y, x, gx, gy, m);
    return m;
}

// Packed direction tables (value+1 in nibbles, dir d at nibble 4d)
#define DX_PACK 0x21000122u
#define DY_PACK 0x00012221u
__device__ __forceinline__ int unpack_d(unsigned pack, int d) {
    return (int)((pack >> (4 * d)) & 0xFu) - 1;
}

__device__ __forceinline__ int orient_k_fast(Smem& sm, float sgx, float sgy,
                                             int cy, int cx) {
    const float ax = fabsf(sgx), ay = fabsf(sgy);
    const bool gxneg = sgx < 0.0f;
    const bool gypos = (__float_as_int(sgy) >= 0);
    int kq;
    bool risky;
    if (!gxneg) {
        const float lo = T1_POS * ax, hi = T2_POS * ax;
        risky = (fabsf(ay - lo) <= BAND1 * ax) || (fabsf(ay - hi) <= BAND2 * ax);
        if (ay < lo)      kq = 4;
        else if (ay < hi) kq = gypos ? 5 : 3;
        else              kq = gypos ? 6 : 2;
    } else {
        const float lo = T1_NEG * ax, hi = T2_NEG * ax;
        risky = (fabsf(ay - lo) <= BAND1 * ax) || (fabsf(ay - hi) <= BAND2 * ax) ||
                (ay <= 1e-3f * ax);
        if (ay < lo)      kq = gypos ? 8 : 0;
        else if (ay < hi) kq = gypos ? 7 : 1;
        else              kq = gypos ? 6 : 2;
    }
    if (risky) kq = orient_k_exact_smem(sm.sblur, cy, cx);
    return kq;
}

// ---------------------------------------------------------------------------
// Per-task bodies (interior fast path)
// ---------------------------------------------------------------------------
__device__ __forceinline__ void a1_task(Smem& sm, const float* __restrict__ img,
                                        float g0, float g1, float g2, float g3,
                                        float g4, int bx0, int by0, int t) {
    const int c = t / ((TH + 8) * 9), rem = t - c * ((TH + 8) * 9);
    const int r = rem / 9, g = rem - r * 9;
    const float* row = img + c * HW + (by0 - 4 + r) * IMG_W + (bx0 + 4 * g - 4);
    const float4 A = __ldg((const float4*)row);
    const float4 B = __ldg((const float4*)(row + 4));
    const float w[8] = {A.x, A.y, A.z, A.w, B.x, B.y, B.z, B.w};
    float o[4];
#pragma unroll
    for (int i = 0; i < 4; i++) {
        float v = g2 * w[i + 2];
        v = fmaf(g0, w[i],     v);
        v = fmaf(g1, w[i + 1], v);
        v = fmaf(g3, w[i + 3], v);
        v = fmaf(g4, w[i + 4], v);
        o[i] = v;
    }
    *(float4*)&sm.u.hbuf[c][r][4 * g] = make_float4(o[0], o[1], o[2], o[3]);
}

__device__ __forceinline__ void a2_task(Smem& sm, float g0, float g1, float g2,
                                        float g3, float g4, int t) {
    const int c = t / ((TH + 4) * 9), rem = t - c * ((TH + 4) * 9);
    const int r = rem / 9, g = rem - r * 9;
    const int ch = 4 * g;
    const float4 h0 = *(const float4*)&sm.u.hbuf[c][r][ch];
    const float4 h1 = *(const float4*)&sm.u.hbuf[c][r + 1][ch];
    const float4 h2 = *(const float4*)&sm.u.hbuf[c][r + 2][ch];
    const float4 h3 = *(const float4*)&sm.u.hbuf[c][r + 3][ch];
    const float4 h4 = *(const float4*)&sm.u.hbuf[c][r + 4][ch];
    float4 o;
    o.x = fmaf(g4, h4.x, fmaf(g3, h3.x, fmaf(g2, h2.x, fmaf(g1, h1.x, g0 * h0.x))));
    o.y = fmaf(g4, h4.y, fmaf(g3, h3.y, fmaf(g2, h2.y, fmaf(g1, h1.y, g0 * h0.y))));
    o.z = fmaf(g4, h4.z, fmaf(g3, h3.z, fmaf(g2, h2.z, fmaf(g1, h1.z, g0 * h0.z))));
    o.w = fmaf(g4, h4.w, fmaf(g3, h3.w, fmaf(g2, h2.w, fmaf(g1, h1.w, g0 * h0.w))));
    *(float4*)&sm.sblur[c][r][4 * g + 4] = o;
}

__device__ __forceinline__ void b_task(Smem& sm, int t) {
    const int r = t / 9, g = t - 9 * r;    // r 0..TH+1
    const int col = 4 * g + 4;
    float m[4]  = {0.f, 0.f, 0.f, 0.f};
    float sx[4] = {0.f, 0.f, 0.f, 0.f};
    float sy[4] = {0.f, 0.f, 0.f, 0.f};
#pragma unroll
    for (int c = 0; c < 3; c++) {
        const float4 L0 = *(const float4*)&sm.sblur[c][r][col];
        const float4 R0 = *(const float4*)&sm.sblur[c][r][col + 4];
        const float4 L1 = *(const float4*)&sm.sblur[c][r + 1][col];
        const float4 R1 = *(const float4*)&sm.sblur[c][r + 1][col + 4];
        const float4 L2 = *(const float4*)&sm.sblur[c][r + 2][col];
        const float4 R2 = *(const float4*)&sm.sblur[c][r + 2][col + 4];
        const float w0[6] = {L0.x, L0.y, L0.z, L0.w, R0.x, R0.y};
        const float w1[6] = {L1.x, L1.y, L1.z, L1.w, R1.x, R1.y};
        const float w2[6] = {L2.x, L2.y, L2.z, L2.w, R2.x, R2.y};
#pragma unroll
        for (int i = 0; i < 4; i++) {
            const float a  = w0[i], b = w0[i + 1], cc = w0[i + 2];
            const float d  = w1[i], e = w1[i + 2];
            const float f  = w2[i], gg = w2[i + 1], h = w2[i + 2];
            const float gx = (a - cc) + 2.0f * (d - e) + (f - h);
            const float gy = (a + 2.0f * b + cc) - (f + 2.0f * gg + h);
            m[i] += sqrt_approx(fmaf(gx, gx, gy * gy));
            sx[i] += gx;
            sy[i] += gy;
        }
    }
    *(float4*)&sm.u.b.smag[r][col] = make_float4(m[0], m[1], m[2], m[3]);
#pragma unroll
    for (int i = 0; i < 4; i++) {
        const int s = 4 * g + i;
        if (r >= 1 && r < TH + 1 && s >= 1 && s < 33) {
            sm.u.b.sk[r - 1][s - 1] =
                (signed char)orient_k_fast(sm, sx[i], sy[i], r - 1, s - 1);
        }
    }
}

// ---------------------------------------------------------------------------
// Border slow path (scalar, zero-padded)
// ---------------------------------------------------------------------------
__device__ __forceinline__ void body_border(
    Smem& sm, const float* __restrict__ img,
    float g0, float g1, float g2, float g3, float g4,
    int bx0, int by0, int tid) {

    // A1 scalar: 3 x (TH+8) x 36
    for (int t = tid; t < 3 * (TH + 8) * 36; t += 512) {
        const int c = t / ((TH + 8) * 36), rem = t - c * ((TH + 8) * 36);
        const int r = rem / 36, s = rem - r * 36;
        const int Y = by0 - 4 + r;
        const int X = bx0 - 2 + s;
        const float* src = img + c * HW;
        float v = g2 * ldz_g(src, Y, X);
        v = fmaf(g0, ldz_g(src, Y, X - 2), v);
        v = fmaf(g1, ldz_g(src, Y, X - 1), v);
        v = fmaf(g3, ldz_g(src, Y, X + 1), v);
        v = fmaf(g4, ldz_g(src, Y, X + 2), v);
        sm.u.hbuf[c][r][s] = v;
    }
    __syncthreads();

    // A2 scalar: 3 x (TH+4) x 36; zero outside image
    for (int t = tid; t < 3 * (TH + 4) * 36; t += 512) {
        const int c = t / ((TH + 4) * 36), rem = t - c * ((TH + 4) * 36);
        const int r = rem / 36, s = rem - r * 36;
        const int Y = by0 - 2 + r, X = bx0 - 2 + s;
        float v = 0.0f;
        if (Y >= 0 && Y < IMG_H && X >= 0 && X < IMG_W) {
            v = g0 * sm.u.hbuf[c][r][s];
            v = fmaf(g1, sm.u.hbuf[c][r + 1][s], v);
            v = fmaf(g2, sm.u.hbuf[c][r + 2][s], v);
            v = fmaf(g3, sm.u.hbuf[c][r + 3][s], v);
            v = fmaf(g4, sm.u.hbuf[c][r + 4][s], v);
        }
        sm.sblur[c][r][s + 4] = v;
    }
    __syncthreads();
}

template <bool BORDER>
__device__ __forceinline__ void canny_tail(
    Smem& sm, int bx0, int by0, int tid,
    float* __restrict__ blurred_out, float* __restrict__ mag_out,
    float* __restrict__ orient_out, float* __restrict__ early_out,
    float* __restrict__ thin_out, float* __restrict__ thresh_out) {

    // ---- blurred output (reads valid after A2 barrier) ----
    {
        const int r = tid >> 3, g = tid & 7;   // r 0..63
#pragma unroll
        for (int c = 0; c < 3; c++) {
            float4 o;
            o.x = sm.sblur[c][r + 2][4 * g + 6];
            o.y = sm.sblur[c][r + 2][4 * g + 7];
            o.z = sm.sblur[c][r + 2][4 * g + 8];
            o.w = sm.sblur[c][r + 2][4 * g + 9];
            *(float4*)&blurred_out[c * HW + (by0 + r) * IMG_W + bx0 + 4 * g] = o;
        }
    }

    // ---- Stage B: (TH+2) x 9 = 594 tasks ----
    if (!BORDER) {
        b_task(sm, tid);
        if (tid < (TH + 2) * 9 - 512) b_task(sm, tid + 512);
    } else {
        for (int t = tid; t < (TH + 2) * 34; t += 512) {
            const int r = t / 34, s = t - 34 * r;
            const int Y = by0 - 1 + r, X = bx0 - 1 + s;
            float m = 0.0f, sgx = 0.0f, sgy = 0.0f;
            if (Y >= 0 && Y < IMG_H && X >= 0 && X < IMG_W) {
#pragma unroll
                for (int c = 0; c < 3; c++) {
                    const float a  = sm.sblur[c][r][s + 4];
                    const float b  = sm.sblur[c][r][s + 5];
                    const float cc = sm.sblur[c][r][s + 6];
                    const float d  = sm.sblur[c][r + 1][s + 4];
                    const float e  = sm.sblur[c][r + 1][s + 6];
                    const float f  = sm.sblur[c][r + 2][s + 4];
                    const float gg = sm.sblur[c][r + 2][s + 5];
                    const float h  = sm.sblur[c][r + 2][s + 6];
                    const float gx = (a - cc) + 2.0f * (d - e) + (f - h);
                    const float gy = (a + 2.0f * b + cc) - (f + 2.0f * gg + h);
                    m += sqrt_approx(fmaf(gx, gx, gy * gy));
                    sgx += gx;
                    sgy += gy;
                }
            }
            sm.u.b.smag[r][s + 4] = m;
            if (r >= 1 && r < TH + 1 && s >= 1 && s < 33) {
                sm.u.b.sk[r - 1][s - 1] =
                    (signed char)orient_k_fast(sm, sgx, sgy, r - 1, s - 1);
            }
        }
    }
    __syncthreads();

    // ---- Stage C: NMS + 5 vector output stores (512 tasks exactly) ----
    {
        const int y = tid >> 3, g = tid & 7;
        const int Y = by0 + y;
        const int Xb = bx0 + 4 * g;
        float vm[4], vo[4], ve[4], vt[4], vh[4];
#pragma unroll
        for (int i = 0; i < 4; i++) {
            const int x = 4 * g + i;
            const float m = sm.u.b.smag[y + 1][x + 5];
            const int kq  = (int)sm.u.b.sk[y][x];

            vm[i] = m;
            vo[i] = 45.0f * (float)kq;
            ve[i] = (m < THRESH) ? 0.0f : m;

            const int ip  = kq & 7;
            const int in_ = (kq + 4) & 7;
            const int pdy = unpack_d(DY_PACK, ip),  pdx = unpack_d(DX_PACK, ip);
            const int ndy = unpack_d(DY_PACK, in_), ndx = unpack_d(DX_PACK, in_);

            const float npos = sm.u.b.smag[y + 1 + pdy][x + 5 + pdx];
            const float nneg = sm.u.b.smag[y + 1 + ndy][x + 5 + ndx];
            const float sel_min = fminf(m - npos, m - nneg);

            bool is_max;
            const float eps = 4e-6f * fmaxf(m, 1.0f);
            if (fabsf(sel_min) > eps) {
                is_max = sel_min > 0.0f;
            } else {
                const double md = mag_exact_smem(sm.sblur, y, x, Y, Xb + i);
                const double dp = md - mag_exact_smem(sm.sblur, y + pdy, x + pdx,
                                                      Y + pdy, Xb + i + pdx);
                const double dn = md - mag_exact_smem(sm.sblur, y + ndy, x + ndx,
                                                      Y + ndy, Xb + i + ndx);
                is_max = fmin(dp, dn) > 0.0;
            }

            const float thin = is_max ? m : 0.0f;
            vt[i] = thin;
            vh[i] = (thin < THRESH) ? 0.0f : thin;
        }
        const int idx = Y * IMG_W + Xb;
        *(float4*)&mag_out[idx]    = make_float4(vm[0], vm[1], vm[2], vm[3]);
        *(float4*)&orient_out[idx] = make_float4(vo[0], vo[1], vo[2], vo[3]);
        *(float4*)&early_out[idx]  = make_float4(ve[0], ve[1], ve[2], ve[3]);
        *(float4*)&thin_out[idx]   = make_float4(vt[0], vt[1], vt[2], vt[3]);
        *(float4*)&thresh_out[idx] = make_float4(vh[0], vh[1], vh[2], vh[3]);
    }
}

__global__ void __launch_bounds__(512, 3)
canny_fused(const float* __restrict__ img,
            const float* __restrict__ g5,
            float* __restrict__ blurred_out,
            float* __restrict__ mag_out,
            float* __restrict__ orient_out,
            float* __restrict__ early_out,
            float* __restrict__ thin_out,
            float* __restrict__ thresh_out) {
    extern __shared__ char smem_raw[];
    Smem& sm = *reinterpret_cast<Smem*>(smem_raw);

    const int tid = threadIdx.x;
    const int bx0 = blockIdx.x * 32;
    const int by0 = blockIdx.y * TH;

    const float g0 = __ldg(g5 + 0), g1 = __ldg(g5 + 1), g2 = __ldg(g5 + 2),
                g3 = __ldg(g5 + 3), g4 = __ldg(g5 + 4);

    const bool interior = (bx0 != 0) && (bx0 != IMG_W - 32) &&
                          (by0 != 0) && (by0 != IMG_H - TH);
    if (interior) {
        // A1: 3 x 72 x 9 = 1944 tasks
        a1_task(sm, img, g0, g1, g2, g3, g4, bx0, by0, tid);
        a1_task(sm, img, g0, g1, g2, g3, g4, bx0, by0, tid + 512);
        a1_task(sm, img, g0, g1, g2, g3, g4, bx0, by0, tid + 1024);
        if (tid < 1944 - 1536)
            a1_task(sm, img, g0, g1, g2, g3, g4, bx0, by0, tid + 1536);
        __syncthreads();

        // A2: 3 x 68 x 9 = 1836 tasks
        a2_task(sm, g0, g1, g2, g3, g4, tid);
        a2_task(sm, g0, g1, g2, g3, g4, tid + 512);
        a2_task(sm, g0, g1, g2, g3, g4, tid + 1024);
        if (tid < 1836 - 1536)
            a2_task(sm, g0, g1, g2, g3, g4, tid + 1536);
        __syncthreads();

        canny_tail<false>(sm, bx0, by0, tid, blurred_out, mag_out, orient_out,
                          early_out, thin_out, thresh_out);
    } else {
        body_border(sm, img, g0, g1, g2, g3, g4, bx0, by0, tid);
        canny_tail<true>(sm, bx0, by0, tid, blurred_out, mag_out, orient_out,
                         early_out, thin_out, thresh_out);
    }
}

// ---------------------------------------------------------------------------
// Output layout (concatenated reference tuple, fp32):
//   [0,3HW) blurred | [3HW,4HW) mag | [4HW,5HW) orient | [5HW,6HW) thin
//   [6HW,7HW) thresholded | [7HW,8HW) early
// ---------------------------------------------------------------------------
extern "C" void kernel_launch(void* const* d_in, const int* in_sizes, int n_in,
                              void* d_out, int out_size) {
    const float* img  = (const float*)d_in[0];
    const float* gh_w = (const float*)d_in[1];

    float* out      = (float*)d_out;
    float* blurred  = out;
    float* mag      = out + 3 * (size_t)HW;
    float* orient   = out + 4 * (size_t)HW;
    float* thin     = out + 5 * (size_t)HW;
    float* threshed = out + 6 * (size_t)HW;
    float* early    = out + 7 * (size_t)HW;

    cudaFuncSetAttribute(canny_fused, cudaFuncAttributeMaxDynamicSharedMemorySize,
                         (int)sizeof(Smem));

    dim3 block(512, 1, 1);
    dim3 grid(IMG_W / 32, IMG_H / TH, 1);
    canny_fused<<<grid, block, sizeof(Smem)>>>(img, gh_w, blurred, mag, orient,
                                               early, thin, threshed);
}

// round 11
// speedup vs baseline: 1.1120x; 1.1120x over previous
#include <cuda_runtime.h>
#include <math.h>

#define IMG_H 2048
#define IMG_W 2048
#define HW (IMG_H * IMG_W)
#define THRESH 10.0f

// 180 / 3.14159 (reference constant, NOT pi)
#define RAD2DEG_D 57.29582790879777437539

// Octant boundary tangents (see R7 derivation)
#define T1_POS 0.41421317376f
#define T2_POS 2.41420677f
#define T1_NEG 0.41421628f
#define T2_NEG 2.41422489f
#define BAND1 1.0e-3f
#define BAND2 6.0e-3f

// Layouts:
//   hbuf[c][r][s]    : h-sum at image (by0-4+r, bx0-2+s), s in 0..35
//   sblur[c][r][s+4] : blurred at image (by0-2+r, bx0-2+s), s in 0..35 (cols 4..39)
//   smag[r][s+4]     : grad mag at image (by0-1+r, bx0-1+s), s in 0..33
//   sk[y][x]         : quantized orientation for central pixel (y,x)
struct Smem {
    union {
        float hbuf[3][40][36];
        struct {
            float smag[34][44];
            signed char sk[32][32];
        } b;
    } u;
    float sblur[3][36][44];
};

__device__ __forceinline__ float ldz_g(const float* __restrict__ p, int Y, int X) {
    return (Y >= 0 && Y < IMG_H && X >= 0 && X < IMG_W) ? __ldg(p + Y * IMG_W + X) : 0.0f;
}

__device__ __forceinline__ float sqrt_approx(float x) {
    float r;
    asm("sqrt.approx.f32 %0, %1;" : "=f"(r) : "f"(x));
    return r;
}

// ---------------------------------------------------------------------------
// Exact (fp64) helpers on the smem blurred tile. (y,x) central coords:
// image (by0+y, bx0+x) = sblur[c][y+2][x+6].
// ---------------------------------------------------------------------------
__device__ __noinline__ void sobel_exact_smem(const float (*sb)[36][44],
                                              int y, int x,
                                              double& ogx, double& ogy, double& omag) {
    double gxs = 0.0, gys = 0.0, mg = 0.0;
#pragma unroll
    for (int c = 0; c < 3; c++) {
        const double a  = sb[c][y + 1][x + 5];
        const double b  = sb[c][y + 1][x + 6];
        const double cc = sb[c][y + 1][x + 7];
        const double d  = sb[c][y + 2][x + 5];
        const double e  = sb[c][y + 2][x + 7];
        const double f  = sb[c][y + 3][x + 5];
        const double g  = sb[c][y + 3][x + 6];
        const double h  = sb[c][y + 3][x + 7];
        const double gx = (a - cc) + 2.0 * (d - e) + (f - h);
        const double gy = (a + 2.0 * b + cc) - (f + 2.0 * g + h);
        gxs += gx; gys += gy;
        mg += sqrt(gx * gx + gy * gy);
    }
    ogx = gxs; ogy = gys; omag = mg;
}

__device__ __noinline__ int orient_k_exact_smem(const float (*sb)[36][44],
                                                int y, int x) {
    double gx, gy, m;
    sobel_exact_smem(sb, y, x, gx, gy, m);
    const double orient = atan2(gy, gx) * RAD2DEG_D + 180.0;
    return (int)rint(orient / 45.0);
}

__device__ __noinline__ double mag_exact_smem(const float (*sb)[36][44],
                                              int y, int x, int Y, int X) {
    if (X < 0 || X >= IMG_W || Y < 0 || Y >= IMG_H) return 0.0;
    double gx, gy, m;
    sobel_exact_smem(sb, y, x, gx, gy, m);
    return m;
}

// Packed direction tables (value+1 in nibbles, dir d at nibble 4d)
#define DX_PACK 0x21000122u
#define DY_PACK 0x00012221u
__device__ __forceinline__ int unpack_d(unsigned pack, int d) {
    return (int)((pack >> (4 * d)) & 0xFu) - 1;
}

__device__ __forceinline__ int orient_k_fast(Smem& sm, float sgx, float sgy,
                                             int cy, int cx) {
    const float ax = fabsf(sgx), ay = fabsf(sgy);
    const bool gxneg = sgx < 0.0f;
    const bool gypos = (__float_as_int(sgy) >= 0);
    int kq;
    bool risky;
    if (!gxneg) {
        const float lo = T1_POS * ax, hi = T2_POS * ax;
        risky = (fabsf(ay - lo) <= BAND1 * ax) || (fabsf(ay - hi) <= BAND2 * ax);
        if (ay < lo)      kq = 4;
        else if (ay < hi) kq = gypos ? 5 : 3;
        else              kq = gypos ? 6 : 2;
    } else {
        const float lo = T1_NEG * ax, hi = T2_NEG * ax;
        risky = (fabsf(ay - lo) <= BAND1 * ax) || (fabsf(ay - hi) <= BAND2 * ax) ||
                (ay <= 1e-3f * ax);
        if (ay < lo)      kq = gypos ? 8 : 0;
        else if (ay < hi) kq = gypos ? 7 : 1;
        else              kq = gypos ? 6 : 2;
    }
    if (risky) kq = orient_k_exact_smem(sm.sblur, cy, cx);
    return kq;
}

// ---------------------------------------------------------------------------
// Per-task bodies (interior fast path)
// ---------------------------------------------------------------------------
__device__ __forceinline__ void a1_task(Smem& sm, const float* __restrict__ img,
                                        float g0, float g1, float g2, float g3,
                                        float g4, int bx0, int by0, int t) {
    const int c = t / 360, rem = t - c * 360;
    const int r = rem / 9, g = rem - r * 9;
    const float* row = img + c * HW + (by0 - 4 + r) * IMG_W + (bx0 + 4 * g - 4);
    const float4 A = __ldg((const float4*)row);
    const float4 B = __ldg((const float4*)(row + 4));
    const float w[8] = {A.x, A.y, A.z, A.w, B.x, B.y, B.z, B.w};
    float o[4];
#pragma unroll
    for (int i = 0; i < 4; i++) {
        float v = g2 * w[i + 2];
        v = fmaf(g0, w[i],     v);
        v = fmaf(g1, w[i + 1], v);
        v = fmaf(g3, w[i + 3], v);
        v = fmaf(g4, w[i + 4], v);
        o[i] = v;
    }
    *(float4*)&sm.u.hbuf[c][r][4 * g] = make_float4(o[0], o[1], o[2], o[3]);
}

// Paired v-blur: computes sblur rows 2*rp and 2*rp+1, sharing 4 of 6 hbuf rows.
// t in [0, 486): c = t/162, rp = (t%162)/9, g = t%9.
__device__ __forceinline__ void a2_pair_task(Smem& sm, float g0, float g1,
                                             float g2, float g3, float g4, int t) {
    const int c = t / 162, rem = t - c * 162;
    const int rp = rem / 9, g = rem - rp * 9;
    const int r0 = 2 * rp;
    const int ch = 4 * g;
    const float4 h0 = *(const float4*)&sm.u.hbuf[c][r0][ch];
    const float4 h1 = *(const float4*)&sm.u.hbuf[c][r0 + 1][ch];
    const float4 h2 = *(const float4*)&sm.u.hbuf[c][r0 + 2][ch];
    const float4 h3 = *(const float4*)&sm.u.hbuf[c][r0 + 3][ch];
    const float4 h4 = *(const float4*)&sm.u.hbuf[c][r0 + 4][ch];
    const float4 h5 = *(const float4*)&sm.u.hbuf[c][r0 + 5][ch];
    float4 o0, o1;
    o0.x = fmaf(g4, h4.x, fmaf(g3, h3.x, fmaf(g2, h2.x, fmaf(g1, h1.x, g0 * h0.x))));
    o0.y = fmaf(g4, h4.y, fmaf(g3, h3.y, fmaf(g2, h2.y, fmaf(g1, h1.y, g0 * h0.y))));
    o0.z = fmaf(g4, h4.z, fmaf(g3, h3.z, fmaf(g2, h2.z, fmaf(g1, h1.z, g0 * h0.z))));
    o0.w = fmaf(g4, h4.w, fmaf(g3, h3.w, fmaf(g2, h2.w, fmaf(g1, h1.w, g0 * h0.w))));
    o1.x = fmaf(g4, h5.x, fmaf(g3, h4.x, fmaf(g2, h3.x, fmaf(g1, h2.x, g0 * h1.x))));
    o1.y = fmaf(g4, h5.y, fmaf(g3, h4.y, fmaf(g2, h3.y, fmaf(g1, h2.y, g0 * h1.y))));
    o1.z = fmaf(g4, h5.z, fmaf(g3, h4.z, fmaf(g2, h3.z, fmaf(g1, h2.z, g0 * h1.z))));
    o1.w = fmaf(g4, h5.w, fmaf(g3, h4.w, fmaf(g2, h3.w, fmaf(g1, h2.w, g0 * h1.w))));
    *(float4*)&sm.sblur[c][r0][4 * g + 4]     = o0;
    *(float4*)&sm.sblur[c][r0 + 1][4 * g + 4] = o1;
}

__device__ __forceinline__ void b_task(Smem& sm, int t) {
    const int r = t / 9, g = t - 9 * r;
    const int col = 4 * g + 4;
    float m[4]  = {0.f, 0.f, 0.f, 0.f};
    float sx[4] = {0.f, 0.f, 0.f, 0.f};
    float sy[4] = {0.f, 0.f, 0.f, 0.f};
#pragma unroll
    for (int c = 0; c < 3; c++) {
        const float4 L0 = *(const float4*)&sm.sblur[c][r][col];
        const float4 R0 = *(const float4*)&sm.sblur[c][r][col + 4];
        const float4 L1 = *(const float4*)&sm.sblur[c][r + 1][col];
        const float4 R1 = *(const float4*)&sm.sblur[c][r + 1][col + 4];
        const float4 L2 = *(const float4*)&sm.sblur[c][r + 2][col];
        const float4 R2 = *(const float4*)&sm.sblur[c][r + 2][col + 4];
        const float w0[6] = {L0.x, L0.y, L0.z, L0.w, R0.x, R0.y};
        const float w1[6] = {L1.x, L1.y, L1.z, L1.w, R1.x, R1.y};
        const float w2[6] = {L2.x, L2.y, L2.z, L2.w, R2.x, R2.y};
#pragma unroll
        for (int i = 0; i < 4; i++) {
            const float a  = w0[i], b = w0[i + 1], cc = w0[i + 2];
            const float d  = w1[i], e = w1[i + 2];
            const float f  = w2[i], gg = w2[i + 1], h = w2[i + 2];
            const float gx = (a - cc) + 2.0f * (d - e) + (f - h);
            const float gy = (a + 2.0f * b + cc) - (f + 2.0f * gg + h);
            m[i] += sqrt_approx(fmaf(gx, gx, gy * gy));
            sx[i] += gx;
            sy[i] += gy;
        }
    }
    *(float4*)&sm.u.b.smag[r][col] = make_float4(m[0], m[1], m[2], m[3]);
#pragma unroll
    for (int i = 0; i < 4; i++) {
        const int s = 4 * g + i;
        if (r >= 1 && r < 33 && s >= 1 && s < 33) {
            sm.u.b.sk[r - 1][s - 1] =
                (signed char)orient_k_fast(sm, sx[i], sy[i], r - 1, s - 1);
        }
    }
}

// ---------------------------------------------------------------------------
// Border slow path (scalar, zero-padded)
// ---------------------------------------------------------------------------
__device__ __forceinline__ void body_border(
    Smem& sm, const float* __restrict__ img,
    float g0, float g1, float g2, float g3, float g4,
    int bx0, int by0, int tid) {

    // A1 scalar: 4320 tasks = 3 x 40 x 36 (hbuf col s, X = bx0-2+s)
    for (int t = tid; t < 4320; t += 256) {
        const int c = t / 1440, rem = t - c * 1440;
        const int r = rem / 36, s = rem - r * 36;
        const int Y = by0 - 4 + r;
        const int X = bx0 - 2 + s;
        const float* src = img + c * HW;
        float v = g2 * ldz_g(src, Y, X);
        v = fmaf(g0, ldz_g(src, Y, X - 2), v);
        v = fmaf(g1, ldz_g(src, Y, X - 1), v);
        v = fmaf(g3, ldz_g(src, Y, X + 1), v);
        v = fmaf(g4, ldz_g(src, Y, X + 2), v);
        sm.u.hbuf[c][r][s] = v;
    }
    __syncthreads();

    // A2 scalar: 3888 tasks = 3 x 36 x 36; zero outside image
    for (int t = tid; t < 3888; t += 256) {
        const int c = t / 1296, rem = t - c * 1296;
        const int r = rem / 36, s = rem - r * 36;
        const int Y = by0 - 2 + r, X = bx0 - 2 + s;
        float v = 0.0f;
        if (Y >= 0 && Y < IMG_H && X >= 0 && X < IMG_W) {
            v = g0 * sm.u.hbuf[c][r][s];
            v = fmaf(g1, sm.u.hbuf[c][r + 1][s], v);
            v = fmaf(g2, sm.u.hbuf[c][r + 2][s], v);
            v = fmaf(g3, sm.u.hbuf[c][r + 3][s], v);
            v = fmaf(g4, sm.u.hbuf[c][r + 4][s], v);
        }
        sm.sblur[c][r][s + 4] = v;
    }
    __syncthreads();
}

template <bool BORDER>
__device__ __forceinline__ void canny_tail(
    Smem& sm, int bx0, int by0, int tid,
    float* __restrict__ blurred_out, float* __restrict__ mag_out,
    float* __restrict__ orient_out, float* __restrict__ early_out,
    float* __restrict__ thin_out, float* __restrict__ thresh_out) {

    // ---- blurred output (reads valid after A2 barrier) ----
    {
        const int r = tid >> 3, g = tid & 7;
#pragma unroll
        for (int c = 0; c < 3; c++) {
            float4 o;
            o.x = sm.sblur[c][r + 2][4 * g + 6];
            o.y = sm.sblur[c][r + 2][4 * g + 7];
            o.z = sm.sblur[c][r + 2][4 * g + 8];
            o.w = sm.sblur[c][r + 2][4 * g + 9];
            *(float4*)&blurred_out[c * HW + (by0 + r) * IMG_W + bx0 + 4 * g] = o;
        }
    }

    // ---- Stage B ----
    if (!BORDER) {
        b_task(sm, tid);
        if (tid < 50) b_task(sm, tid + 256);
    } else {
        // scalar: 1156 tasks = 34 x 34
        for (int t = tid; t < 1156; t += 256) {
            const int r = t / 34, s = t - 34 * r;
            const int Y = by0 - 1 + r, X = bx0 - 1 + s;
            float m = 0.0f, sgx = 0.0f, sgy = 0.0f;
            if (Y >= 0 && Y < IMG_H && X >= 0 && X < IMG_W) {
#pragma unroll
                for (int c = 0; c < 3; c++) {
                    const float a  = sm.sblur[c][r][s + 4];
                    const float b  = sm.sblur[c][r][s + 5];
                    const float cc = sm.sblur[c][r][s + 6];
                    const float d  = sm.sblur[c][r + 1][s + 4];
                    const float e  = sm.sblur[c][r + 1][s + 6];
                    const float f  = sm.sblur[c][r + 2][s + 4];
                    const float gg = sm.sblur[c][r + 2][s + 5];
                    const float h  = sm.sblur[c][r + 2][s + 6];
                    const float gx = (a - cc) + 2.0f * (d - e) + (f - h);
                    const float gy = (a + 2.0f * b + cc) - (f + 2.0f * gg + h);
                    m += sqrt_approx(fmaf(gx, gx, gy * gy));
                    sgx += gx;
                    sgy += gy;
                }
            }
            sm.u.b.smag[r][s + 4] = m;
            if (r >= 1 && r < 33 && s >= 1 && s < 33) {
                sm.u.b.sk[r - 1][s - 1] =
                    (signed char)orient_k_fast(sm, sgx, sgy, r - 1, s - 1);
            }
        }
    }
    __syncthreads();

    // ---- Stage C: NMS + 5 vector output stores (256 tasks exactly) ----
    {
        const int y = tid >> 3, g = tid & 7;
        const int Y = by0 + y;
        const int Xb = bx0 + 4 * g;
        float vm[4], vo[4], ve[4], vt[4], vh[4];
#pragma unroll
        for (int i = 0; i < 4; i++) {
            const int x = 4 * g + i;
            const float m = sm.u.b.smag[y + 1][x + 5];
            const int kq  = (int)sm.u.b.sk[y][x];

            vm[i] = m;
            vo[i] = 45.0f * (float)kq;
            ve[i] = (m < THRESH) ? 0.0f : m;

            const int ip  = kq & 7;
            const int in_ = (kq + 4) & 7;
            const int pdy = unpack_d(DY_PACK, ip),  pdx = unpack_d(DX_PACK, ip);
            const int ndy = unpack_d(DY_PACK, in_), ndx = unpack_d(DX_PACK, in_);

            const float npos = sm.u.b.smag[y + 1 + pdy][x + 5 + pdx];
            const float nneg = sm.u.b.smag[y + 1 + ndy][x + 5 + ndx];
            const float sel_min = fminf(m - npos, m - nneg);

            bool is_max;
            const float eps = 4e-6f * fmaxf(m, 1.0f);
            if (fabsf(sel_min) > eps) {
                is_max = sel_min > 0.0f;
            } else {
                const double md = mag_exact_smem(sm.sblur, y, x, Y, Xb + i);
                const double dp = md - mag_exact_smem(sm.sblur, y + pdy, x + pdx,
                                                      Y + pdy, Xb + i + pdx);
                const double dn = md - mag_exact_smem(sm.sblur, y + ndy, x + ndx,
                                                      Y + ndy, Xb + i + ndx);
                is_max = fmin(dp, dn) > 0.0;
            }

            const float thin = is_max ? m : 0.0f;
            vt[i] = thin;
            vh[i] = (thin < THRESH) ? 0.0f : thin;
        }
        const int idx = Y * IMG_W + Xb;
        *(float4*)&mag_out[idx]    = make_float4(vm[0], vm[1], vm[2], vm[3]);
        *(float4*)&orient_out[idx] = make_float4(vo[0], vo[1], vo[2], vo[3]);
        *(float4*)&early_out[idx]  = make_float4(ve[0], ve[1], ve[2], ve[3]);
        *(float4*)&thin_out[idx]   = make_float4(vt[0], vt[1], vt[2], vt[3]);
        *(float4*)&thresh_out[idx] = make_float4(vh[0], vh[1], vh[2], vh[3]);
    }
}

__global__ void __launch_bounds__(256, 6)
canny_fused(const float* __restrict__ img,
            const float* __restrict__ g5,
            float* __restrict__ blurred_out,
            float* __restrict__ mag_out,
            float* __restrict__ orient_out,
            float* __restrict__ early_out,
            float* __restrict__ thin_out,
            float* __restrict__ thresh_out) {
    __shared__ Smem sm;

    const int tid = threadIdx.x;
    const int bx0 = blockIdx.x * 32;
    const int by0 = blockIdx.y * 32;

    const float g0 = __ldg(g5 + 0), g1 = __ldg(g5 + 1), g2 = __ldg(g5 + 2),
                g3 = __ldg(g5 + 3), g4 = __ldg(g5 + 4);

    const bool interior = (bx0 != 0) && (bx0 != IMG_W - 32) &&
                          (by0 != 0) && (by0 != IMG_H - 32);
    if (interior) {
        // A1: 1080 tasks, fixed-trip unrolled for ILP/MLP
        a1_task(sm, img, g0, g1, g2, g3, g4, bx0, by0, tid);
        a1_task(sm, img, g0, g1, g2, g3, g4, bx0, by0, tid + 256);
        a1_task(sm, img, g0, g1, g2, g3, g4, bx0, by0, tid + 512);
        a1_task(sm, img, g0, g1, g2, g3, g4, bx0, by0, tid + 768);
        if (tid < 56) a1_task(sm, img, g0, g1, g2, g3, g4, bx0, by0, tid + 1024);
        __syncthreads();

        // A2: 486 paired tasks (972 output rows)
        a2_pair_task(sm, g0, g1, g2, g3, g4, tid);
        if (tid < 230) a2_pair_task(sm, g0, g1, g2, g3, g4, tid + 256);
        __syncthreads();

        canny_tail<false>(sm, bx0, by0, tid, blurred_out, mag_out, orient_out,
                          early_out, thin_out, thresh_out);
    } else {
        body_border(sm, img, g0, g1, g2, g3, g4, bx0, by0, tid);
        canny_tail<true>(sm, bx0, by0, tid, blurred_out, mag_out, orient_out,
                         early_out, thin_out, thresh_out);
    }
}

// ---------------------------------------------------------------------------
// Output layout (concatenated reference tuple, fp32):
//   [0,3HW) blurred | [3HW,4HW) mag | [4HW,5HW) orient | [5HW,6HW) thin
//   [6HW,7HW) thresholded | [7HW,8HW) early
// ---------------------------------------------------------------------------
extern "C" void kernel_launch(void* const* d_in, const int* in_sizes, int n_in,
                              void* d_out, int out_size) {
    const float* img  = (const float*)d_in[0];
    const float* gh_w = (const float*)d_in[1];

    float* out      = (float*)d_out;
    float* blurred  = out;
    float* mag      = out + 3 * (size_t)HW;
    float* orient   = out + 4 * (size_t)HW;
    float* thin     = out + 5 * (size_t)HW;
    float* threshed = out + 6 * (size_t)HW;
    float* early    = out + 7 * (size_t)HW;

    dim3 block(256, 1, 1);
    dim3 grid(IMG_W / 32, IMG_H / 32, 1);
    canny_fused<<<grid, block>>>(img, gh_w, blurred, mag, orient, early,
                                 thin, threshed);
}